// round 14
// baseline (speedup 1.0000x reference)
#include <cuda_runtime.h>
#include <cuda_bf16.h>
#include <math.h>
#include <stdint.h>

// ---------------- problem constants ----------------
#define NE_    100000
#define NR_    200
#define RDIM_  384
#define BB     8192
#define NCOL   406          // 6 scalar cols + 2*NR
#define GAMMA_F 12.0f
#define TSLICE 4            // t in [0,1000) sliced into 4 ranges of 250
#define TSPAN  250
#define CAP    112          // bucket capacity per (row, side, slice)
#define RB     38           // row-blocks per slice: 4*38 = 152 blocks = 1 wave
#define ROWS_PER_BLK 216

#define LOGK (13.287712379549449f / 128.0f)   // log2(10000)/128

// ---------------- scratch (__device__ globals; no allocs allowed) ----------------
__device__ float    g_P[2 * BB * 256];               // e_p: s rows [0,B), o rows [B,2B) (16 MB)
__device__ float    g_scabs[BB];                     // per-row sc_abs
__device__ float2   g_TWb[8 * BB * CAP];             // bucketed (t_local, w) (59 MB)
__device__ int      g_cnt[8 * BB];                   // bucket counts
__device__ unsigned g_Tb[1000 * 32 * 4];             // bf16x2 table: (t,lane)->uint4 of 4 d's (512 KB)
__device__ float    g_part[8 * BB * 256];            // partials per [slice*2+side][row] (64 MB)
__device__ __align__(16) __nv_bfloat16 g_WcT[256 * 512];  // bf16 B^T: WcT[n][k] (256 KB)

// ======================================================================
// Launch 1: fused pre-kernel. Blocks [0,256): fold w_e -> WcT.
// Blocks [256,506): build bf16 pos-emb table (4 t's per block, 512 thr).
// ======================================================================
__global__ void __launch_bounds__(512) k_pre(const float* __restrict__ w_e) {
    const int bid = blockIdx.x;
    const int tid = threadIdx.x;
    if (bid < 256) {
        // WcT[n][k] = Wc[k][n] folded from w_e
        int n = bid, k = tid;
        float v;
        if (n < 128) {
            v = w_e[k * 128 + n];
            if (k >= 256) v = -v;
        } else {
            v = w_e[(k ^ 256) * 128 + (n - 128)];
            if (k < 256) v = -v;
        }
        g_WcT[n * 512 + k] = __float2bfloat16(v);
    } else {
        // table: 4 t's per block
        int t = (bid - 256) * 4 + (tid >> 7);
        int d = tid & 127;
        float f = exp2f(-(float)d * LOGK);
        float s, c;
        sincosf((float)t * f, &s, &c);
        __nv_bfloat162 h2 = __floats2bfloat162_rn(c, s);
        g_Tb[(t * 32 + (d >> 2)) * 4 + (d & 3)] = *reinterpret_cast<unsigned*>(&h2);
    }
}

// ======================================================================
// GEMM path (blocks 0..255 of k_main): bf16 HMMA m16n8k16, fp32 acc.
//   P[m][n] = sum_k A[m][k] * WcT[n][k];  BM=128,BN=128,BK=32, 8 warps
// ======================================================================
#define PADK 40

__device__ __forceinline__ void mma16816(float* c, const uint32_t* a, const uint32_t* b) {
    asm volatile(
        "mma.sync.aligned.m16n8k16.row.col.f32.bf16.bf16.f32 "
        "{%0,%1,%2,%3}, {%4,%5,%6,%7}, {%8,%9}, {%0,%1,%2,%3};"
        : "+f"(c[0]), "+f"(c[1]), "+f"(c[2]), "+f"(c[3])
        : "r"(a[0]), "r"(a[1]), "r"(a[2]), "r"(a[3]), "r"(b[0]), "r"(b[1]));
}

__device__ void gemm_path(const float* __restrict__ e_emb,
                          const int* __restrict__ x, int xs, int bid)
{
    __shared__ __nv_bfloat16 As[128 * PADK];   // 10 KB
    __shared__ __nv_bfloat16 Bs[128 * PADK];   // 10 KB
    __shared__ int idx_s[128];

    const int tid  = threadIdx.x;
    const int wid  = tid >> 5;
    const int lane = tid & 31;
    const int bn = (bid & 1) * 128;
    const int bm = (bid >> 1) * 128;

    if (tid < 128) {
        int gr = bm + tid;
        idx_s[tid] = (gr < BB) ? x[(gr * NCOL + 0) * xs]
                               : x[((gr - BB) * NCOL + 2) * xs];
    }
    __syncthreads();

    const int wm = wid & 1;
    const int wn = wid >> 1;
    const int gid = lane >> 2;          // 0..7
    const int tig = lane & 3;           // 0..3

    const int sr = tid >> 1;            // A row / B n-row (0..127)
    const int sk = (tid & 1) * 16;      // k half (0 or 16)
    const float4* aptr = reinterpret_cast<const float4*>(
        e_emb + (size_t)idx_s[sr] * 512);
    const uint4* bptr = reinterpret_cast<const uint4*>(
        g_WcT + (size_t)(bn + sr) * 512);

    float acc[4][4][4];
    #pragma unroll
    for (int i = 0; i < 4; i++)
        #pragma unroll
        for (int j = 0; j < 4; j++)
            #pragma unroll
            for (int e = 0; e < 4; e++) acc[i][j][e] = 0.0f;

    for (int k0 = 0; k0 < 512; k0 += 32) {
        {
            float4 f0 = __ldg(aptr + ((k0 + sk) >> 2) + 0);
            float4 f1 = __ldg(aptr + ((k0 + sk) >> 2) + 1);
            float4 f2 = __ldg(aptr + ((k0 + sk) >> 2) + 2);
            float4 f3 = __ldg(aptr + ((k0 + sk) >> 2) + 3);
            __nv_bfloat162 h0 = __floats2bfloat162_rn(f0.x, f0.y);
            __nv_bfloat162 h1 = __floats2bfloat162_rn(f0.z, f0.w);
            __nv_bfloat162 h2 = __floats2bfloat162_rn(f1.x, f1.y);
            __nv_bfloat162 h3 = __floats2bfloat162_rn(f1.z, f1.w);
            __nv_bfloat162 h4 = __floats2bfloat162_rn(f2.x, f2.y);
            __nv_bfloat162 h5 = __floats2bfloat162_rn(f2.z, f2.w);
            __nv_bfloat162 h6 = __floats2bfloat162_rn(f3.x, f3.y);
            __nv_bfloat162 h7 = __floats2bfloat162_rn(f3.z, f3.w);
            uint4 q0, q1;
            q0.x = *reinterpret_cast<unsigned*>(&h0);
            q0.y = *reinterpret_cast<unsigned*>(&h1);
            q0.z = *reinterpret_cast<unsigned*>(&h2);
            q0.w = *reinterpret_cast<unsigned*>(&h3);
            q1.x = *reinterpret_cast<unsigned*>(&h4);
            q1.y = *reinterpret_cast<unsigned*>(&h5);
            q1.z = *reinterpret_cast<unsigned*>(&h6);
            q1.w = *reinterpret_cast<unsigned*>(&h7);
            *reinterpret_cast<uint4*>(&As[sr * PADK + sk])     = q0;
            *reinterpret_cast<uint4*>(&As[sr * PADK + sk + 8]) = q1;
        }
        {
            uint4 q0 = __ldg(bptr + ((k0 + sk) >> 3) + 0);
            uint4 q1 = __ldg(bptr + ((k0 + sk) >> 3) + 1);
            *reinterpret_cast<uint4*>(&Bs[sr * PADK + sk])     = q0;
            *reinterpret_cast<uint4*>(&Bs[sr * PADK + sk + 8]) = q1;
        }
        __syncthreads();

        #pragma unroll
        for (int ks = 0; ks < 32; ks += 16) {
            uint32_t afr[4][4], bfr[4][2];
            #pragma unroll
            for (int i = 0; i < 4; i++) {
                int row = wm * 64 + i * 16 + gid;
                afr[i][0] = *reinterpret_cast<const uint32_t*>(&As[row * PADK + ks + tig * 2]);
                afr[i][1] = *reinterpret_cast<const uint32_t*>(&As[(row + 8) * PADK + ks + tig * 2]);
                afr[i][2] = *reinterpret_cast<const uint32_t*>(&As[row * PADK + ks + 8 + tig * 2]);
                afr[i][3] = *reinterpret_cast<const uint32_t*>(&As[(row + 8) * PADK + ks + 8 + tig * 2]);
            }
            #pragma unroll
            for (int j = 0; j < 4; j++) {
                int nc = wn * 32 + j * 8 + gid;
                bfr[j][0] = *reinterpret_cast<const uint32_t*>(&Bs[nc * PADK + ks + tig * 2]);
                bfr[j][1] = *reinterpret_cast<const uint32_t*>(&Bs[nc * PADK + ks + 8 + tig * 2]);
            }
            #pragma unroll
            for (int i = 0; i < 4; i++)
                #pragma unroll
                for (int j = 0; j < 4; j++)
                    mma16816(acc[i][j], afr[i], bfr[j]);
        }
        __syncthreads();
    }

    #pragma unroll
    for (int i = 0; i < 4; i++) {
        int row = bm + wm * 64 + i * 16 + gid;
        #pragma unroll
        for (int j = 0; j < 4; j++) {
            int col = bn + wn * 32 + j * 8 + tig * 2;
            *reinterpret_cast<float2*>(&g_P[(size_t)row * 256 + col]) =
                make_float2(acc[i][j][0], acc[i][j][1]);
            *reinterpret_cast<float2*>(&g_P[(size_t)(row + 8) * 256 + col]) =
                make_float2(acc[i][j][2], acc[i][j][3]);
        }
    }
}

// ======================================================================
// Gather path (blocks 256..8447 of k_main): bucket (t,w), t_emb, sc_abs
// ======================================================================
__device__ void gather_path(
    const int* __restrict__ x, int xs,
    const float* __restrict__ e_emb,
    const float* __restrict__ r_emb,
    const float* __restrict__ d_frq, const float* __restrict__ d_phi,
    const float* __restrict__ d_amp,
    const float* __restrict__ m_frq, const float* __restrict__ m_phi,
    const float* __restrict__ m_amp,
    const float* __restrict__ w_rp, int b)
{
    __shared__ float st[256];
    __shared__ float ot[256];
    __shared__ float red8[8];
    __shared__ int   scnt[8];

    const int tid = threadIdx.x;
    const int base = b * NCOL;

    if (tid < 8) scnt[tid] = 0;
    __syncthreads();

    const int s_idx = x[(base + 0) * xs];
    const int r_idx = x[(base + 1) * xs];
    const int o_idx = x[(base + 2) * xs];
    const float dv  = (float)x[(base + 3) * xs];
    const float mv  = (float)x[(base + 4) * xs];

    for (int i = tid; i < 400; i += 256) {
        int side = (i >= 200);
        int n    = i - side * 200;
        int t    = x[(base + 6 + i) * xs];
        float w  = w_rp[r_idx * 200 + n];
        int slice = t / TSPAN;
        int idx8  = slice * 2 + side;
        int pos = atomicAdd(&scnt[idx8], 1);
        if (pos < CAP)
            g_TWb[((size_t)idx8 * BB + b) * CAP + pos] =
                make_float2((float)(t - slice * TSPAN), w);
    }

    {
        const int j  = tid;
        const int jm = (j < 128) ? j : (j - 128);
        {
            const size_t e = (size_t)s_idx;
            float angd = fmaf(dv, d_frq[e * 256 + j], d_phi[e * 256 + j]);
            float angm = fmaf(mv, m_frq[e * 256 + j], m_phi[e * 256 + j]);
            float ad = d_amp[e * 128 + jm];
            float am = m_amp[e * 128 + jm];
            st[j] = (j < 128) ? (ad * __cosf(angd) + am * __cosf(angm))
                              : (ad * __sinf(angd) + am * __sinf(angm));
        }
        {
            const size_t e = (size_t)o_idx;
            float angd = fmaf(dv, d_frq[e * 256 + j], d_phi[e * 256 + j]);
            float angm = fmaf(mv, m_frq[e * 256 + j], m_phi[e * 256 + j]);
            float ad = d_amp[e * 128 + jm];
            float am = m_amp[e * 128 + jm];
            ot[j] = (j < 128) ? (ad * __cosf(angd) + am * __cosf(angm))
                              : (ad * __sinf(angd) + am * __sinf(angm));
        }
    }
    __syncthreads();

    if (tid < 8) g_cnt[(size_t)tid * BB + b] = min(scnt[tid], CAP);

    const float scale = (float)(3.141592653589793 / sqrt(6.0 / (double)(NR_ + RDIM_)));
    const size_t sb = (size_t)s_idx * 512;
    const size_t ob = (size_t)o_idx * 512;
    float sum = 0.0f;
    for (int k = tid; k < 384; k += 256) {
        float pr = r_emb[(size_t)r_idx * 384 + k] * scale;
        float sn, cs;
        __sincosf(pr, &sn, &cs);
        float re_s, im_s, re_o, im_o;
        if (k < 256) {
            re_s = e_emb[sb + k];
            im_s = e_emb[sb + 256 + k];
            re_o = e_emb[ob + k];
            im_o = e_emb[ob + 256 + k];
        } else {
            re_s = st[k - 256];  im_s = st[k - 128];
            re_o = ot[k - 256];  im_o = ot[k - 128];
        }
        float re = re_s * cs - im_s * sn - re_o;
        float im = re_s * sn + im_s * cs - im_o;
        sum += sqrtf(re * re + im * im);
    }

    #pragma unroll
    for (int off = 16; off; off >>= 1) sum += __shfl_down_sync(0xffffffffu, sum, off);
    if ((tid & 31) == 0) red8[tid >> 5] = sum;
    __syncthreads();
    if (tid == 0) {
        float t = 0.0f;
        #pragma unroll
        for (int i = 0; i < 8; i++) t += red8[i];
        g_scabs[b] = t;
    }
}

// ======================================================================
// Launch 2: fused main kernel — gemm blocks first, gather after.
// ======================================================================
__global__ void __launch_bounds__(256) k_main(
    const int* __restrict__ x, int xs,
    const float* __restrict__ e_emb,
    const float* __restrict__ r_emb,
    const float* __restrict__ d_frq, const float* __restrict__ d_phi,
    const float* __restrict__ d_amp,
    const float* __restrict__ m_frq, const float* __restrict__ m_phi,
    const float* __restrict__ m_amp,
    const float* __restrict__ w_rp)
{
    const int bid = blockIdx.x;
    if (bid < 256) {
        gemm_path(e_emb, x, xs, bid);
    } else {
        gather_path(x, xs, e_emb, r_emb, d_frq, d_phi, d_amp,
                    m_frq, m_phi, m_amp, w_rp, bid - 256);
    }
}

// ======================================================================
// Launch 3: e_r_emb partials, t-sliced bf16 table (unchanged from R11)
// ======================================================================
__global__ void __launch_bounds__(512, 1) k_rel() {
    extern __shared__ uint4 ts[];              // [250*32] uint4 = 128 KB
    const int tid   = threadIdx.x;
    const int slice = blockIdx.x & 3;
    const int bj    = blockIdx.x >> 2;         // 0..37
    const int row_begin = bj * ROWS_PER_BLK;
    const int row_end   = min(BB, row_begin + ROWS_PER_BLK);

    {
        const uint4* gt4 = reinterpret_cast<const uint4*>(g_Tb) + (size_t)slice * 8000;
        for (int i = tid; i < 8000; i += 512) ts[i] = gt4[i];
    }
    __syncthreads();

    const int lane = tid & 31;
    const int wid  = tid >> 5;

    for (int row = row_begin + wid; row < row_end; row += 16) {
        #pragma unroll
        for (int side = 0; side < 2; side++) {
            const int idx8 = slice * 2 + side;
            const int cnt  = g_cnt[(size_t)idx8 * BB + row];
            const float2* tw = g_TWb + ((size_t)idx8 * BB + row) * CAP;

            float re0 = 0.f, im0 = 0.f, re1 = 0.f, im1 = 0.f;
            float re2 = 0.f, im2 = 0.f, re3 = 0.f, im3 = 0.f;

            int i = 0;
            #pragma unroll 2
            for (; i + 2 <= cnt; i += 2) {
                float4 v = __ldg(reinterpret_cast<const float4*>(tw + i));
                {
                    uint4 q = ts[(int)v.x * 32 + lane];
                    float2 c0 = __bfloat1622float2(*reinterpret_cast<__nv_bfloat162*>(&q.x));
                    float2 c1 = __bfloat1622float2(*reinterpret_cast<__nv_bfloat162*>(&q.y));
                    float2 c2 = __bfloat1622float2(*reinterpret_cast<__nv_bfloat162*>(&q.z));
                    float2 c3 = __bfloat1622float2(*reinterpret_cast<__nv_bfloat162*>(&q.w));
                    re0 = fmaf(v.y, c0.x, re0); im0 = fmaf(v.y, c0.y, im0);
                    re1 = fmaf(v.y, c1.x, re1); im1 = fmaf(v.y, c1.y, im1);
                    re2 = fmaf(v.y, c2.x, re2); im2 = fmaf(v.y, c2.y, im2);
                    re3 = fmaf(v.y, c3.x, re3); im3 = fmaf(v.y, c3.y, im3);
                }
                {
                    uint4 q = ts[(int)v.z * 32 + lane];
                    float2 c0 = __bfloat1622float2(*reinterpret_cast<__nv_bfloat162*>(&q.x));
                    float2 c1 = __bfloat1622float2(*reinterpret_cast<__nv_bfloat162*>(&q.y));
                    float2 c2 = __bfloat1622float2(*reinterpret_cast<__nv_bfloat162*>(&q.z));
                    float2 c3 = __bfloat1622float2(*reinterpret_cast<__nv_bfloat162*>(&q.w));
                    re0 = fmaf(v.w, c0.x, re0); im0 = fmaf(v.w, c0.y, im0);
                    re1 = fmaf(v.w, c1.x, re1); im1 = fmaf(v.w, c1.y, im1);
                    re2 = fmaf(v.w, c2.x, re2); im2 = fmaf(v.w, c2.y, im2);
                    re3 = fmaf(v.w, c3.x, re3); im3 = fmaf(v.w, c3.y, im3);
                }
            }
            if (i < cnt) {
                float2 v = __ldg(tw + i);
                uint4 q = ts[(int)v.x * 32 + lane];
                float2 c0 = __bfloat1622float2(*reinterpret_cast<__nv_bfloat162*>(&q.x));
                float2 c1 = __bfloat1622float2(*reinterpret_cast<__nv_bfloat162*>(&q.y));
                float2 c2 = __bfloat1622float2(*reinterpret_cast<__nv_bfloat162*>(&q.z));
                float2 c3 = __bfloat1622float2(*reinterpret_cast<__nv_bfloat162*>(&q.w));
                re0 = fmaf(v.y, c0.x, re0); im0 = fmaf(v.y, c0.y, im0);
                re1 = fmaf(v.y, c1.x, re1); im1 = fmaf(v.y, c1.y, im1);
                re2 = fmaf(v.y, c2.x, re2); im2 = fmaf(v.y, c2.y, im2);
                re3 = fmaf(v.y, c3.x, re3); im3 = fmaf(v.y, c3.y, im3);
            }

            float* dst = g_part + ((size_t)idx8 * BB + row) * 256;
            *reinterpret_cast<float4*>(dst + 4 * lane)       = make_float4(re0, re1, re2, re3);
            *reinterpret_cast<float4*>(dst + 128 + 4 * lane) = make_float4(im0, im1, im2, im3);
        }
    }
}

// ======================================================================
// Launch 4: combine (unchanged from R11)
// ======================================================================
__global__ void __launch_bounds__(128) k_comb(float* __restrict__ out) {
    __shared__ float red4[4];
    const int row = blockIdx.x;
    const int d   = threadIdx.x;   // 0..127

    float rs = 0.f, is = 0.f, ro = 0.f, io = 0.f;
    #pragma unroll
    for (int t = 0; t < TSLICE; t++) {
        const float* ps = g_part + ((size_t)(t * 2 + 0) * BB + row) * 256;
        const float* po = g_part + ((size_t)(t * 2 + 1) * BB + row) * 256;
        rs += ps[d]; is += ps[128 + d];
        ro += po[d]; io += po[128 + d];
    }
    const float* Ps = g_P + (size_t)row * 256;
    const float* Po = g_P + (size_t)(BB + row) * 256;
    rs += Ps[d]; is += Ps[128 + d];
    ro += Po[d]; io += Po[128 + d];

    float dre = rs - ro, dim = is - io;
    float v = sqrtf(dre * dre + dim * dim);

    #pragma unroll
    for (int off = 16; off; off >>= 1) v += __shfl_down_sync(0xffffffffu, v, off);
    if ((d & 31) == 0) red4[d >> 5] = v;
    __syncthreads();
    if (d == 0)
        out[row] = GAMMA_F - (g_scabs[row] + red4[0] + red4[1] + red4[2] + red4[3]);
}

// ======================================================================
// launcher
// ======================================================================
extern "C" void kernel_launch(void* const* d_in, const int* in_sizes, int n_in,
                              void* d_out, int out_size)
{
    const int*   x     = (const int*)  d_in[0];
    const float* e_emb = (const float*)d_in[1];
    const float* r_emb = (const float*)d_in[2];
    const float* d_frq = (const float*)d_in[3];
    const float* d_phi = (const float*)d_in[4];
    const float* d_amp = (const float*)d_in[5];
    const float* m_frq = (const float*)d_in[6];
    const float* m_phi = (const float*)d_in[7];
    const float* m_amp = (const float*)d_in[8];
    const float* w_e   = (const float*)d_in[9];
    const float* w_rp  = (const float*)d_in[10];
    float* out = (float*)d_out;

    int xs = in_sizes[0] / (BB * NCOL);
    if (xs < 1) xs = 1;

    cudaFuncSetAttribute(k_rel, cudaFuncAttributeMaxDynamicSharedMemorySize, 128 * 1024);

    k_pre<<<506, 512>>>(w_e);
    k_main<<<256 + BB, 256>>>(x, xs, e_emb, r_emb, d_frq, d_phi, d_amp,
                              m_frq, m_phi, m_amp, w_rp);
    k_rel<<<TSLICE * RB, 512, 128 * 1024>>>();
    k_comb<<<BB, 128>>>(out);
}

// round 15
// speedup vs baseline: 2.9058x; 2.9058x over previous
#include <cuda_runtime.h>
#include <cuda_bf16.h>
#include <math.h>
#include <stdint.h>

// ---------------- problem constants ----------------
#define NE_    100000
#define NR_    200
#define RDIM_  384
#define BB     8192
#define NCOL   406          // 6 scalar cols + 2*NR
#define GAMMA_F 12.0f
#define KA     512          // Adiff K-region
#define KW     1024         // W (t-histogram) K-region, t in [0,1000) zero-padded
#define KTOT   (KA + KW)    // 1536

#define LOGK (13.287712379549449f / 128.0f)   // log2(10000)/128

// ---------------- scratch (__device__ globals; no allocs allowed) ----------------
__device__ float    g_scabs[BB];                          // per-row sc_abs
__device__ __align__(16) __nv_bfloat16 g_AB[BB * KTOT];   // A: [Adiff | W] per row (24 MB)
__device__ __align__(16) __nv_bfloat16 g_Bm[256 * KTOT];  // B: [Wc ; PosTable] (768 KB)
__device__ float    g_D[BB * 256];                        // GEMM result (8 MB)

// ======================================================================
// Launch 1: build B operand g_Bm[n][k]:
//   k <  512       : folded Wc^T  (n<128 re-coeffs, n>=128 im-coeffs)
//   512 <= k < 1512: t = k-512;  n<128 -> cos(t*f_n), n>=128 -> sin(t*f_{n-128})
//   k >= 1512      : 0
// ======================================================================
__global__ void __launch_bounds__(512) k_pre(const float* __restrict__ w_e) {
    const int n = blockIdx.x;       // 0..255
    const int tid = threadIdx.x;
    const float f = exp2f(-(float)(n & 127) * LOGK);
    for (int k = tid; k < KTOT; k += 512) {
        float v;
        if (k < KA) {
            if (n < 128) {
                v = w_e[k * 128 + n];
                if (k >= 256) v = -v;
            } else {
                v = w_e[(k ^ 256) * 128 + (n - 128)];
                if (k < 256) v = -v;
            }
        } else if (k < KA + 1000) {
            float t = (float)(k - KA);
            float s, c;
            sincosf(t * f, &s, &c);
            v = (n < 128) ? c : s;
        } else {
            v = 0.0f;
        }
        g_Bm[n * KTOT + k] = __float2bfloat16(v);
    }
}

// ======================================================================
// Launch 2: per row — signed t-histogram W (smem scatter), Adiff,
//           t_emb, sc_abs.  One block (256 thr) per row.
// ======================================================================
__global__ void __launch_bounds__(256) k_gather(
    const int* __restrict__ x, int xs,
    const float* __restrict__ e_emb,
    const float* __restrict__ r_emb,
    const float* __restrict__ d_frq, const float* __restrict__ d_phi,
    const float* __restrict__ d_amp,
    const float* __restrict__ m_frq, const float* __restrict__ m_phi,
    const float* __restrict__ m_amp,
    const float* __restrict__ w_rp)
{
    __shared__ float Wrow[KW];      // signed histogram over t
    __shared__ float st[256];
    __shared__ float ot[256];
    __shared__ float red8[8];

    const int b   = blockIdx.x;
    const int tid = threadIdx.x;
    const int base = b * NCOL;

    #pragma unroll
    for (int i = 0; i < 4; i++) Wrow[tid + i * 256] = 0.0f;
    __syncthreads();

    const int s_idx = x[(base + 0) * xs];
    const int r_idx = x[(base + 1) * xs];
    const int o_idx = x[(base + 2) * xs];
    const float dv  = (float)x[(base + 3) * xs];
    const float mv  = (float)x[(base + 4) * xs];

    // ---- signed scatter: +w for s-side t's, -w for o-side t's ----
    for (int i = tid; i < 400; i += 256) {
        int side = (i >= 200);
        int n    = i - side * 200;
        int t    = x[(base + 6 + i) * xs];
        float w  = w_rp[r_idx * 200 + n];
        atomicAdd(&Wrow[t], side ? -w : w);
    }

    // ---- t_emb (j = tid covers all 256 dims) ----
    {
        const int j  = tid;
        const int jm = (j < 128) ? j : (j - 128);
        {
            const size_t e = (size_t)s_idx;
            float angd = fmaf(dv, d_frq[e * 256 + j], d_phi[e * 256 + j]);
            float angm = fmaf(mv, m_frq[e * 256 + j], m_phi[e * 256 + j]);
            float ad = d_amp[e * 128 + jm];
            float am = m_amp[e * 128 + jm];
            st[j] = (j < 128) ? (ad * __cosf(angd) + am * __cosf(angm))
                              : (ad * __sinf(angd) + am * __sinf(angm));
        }
        {
            const size_t e = (size_t)o_idx;
            float angd = fmaf(dv, d_frq[e * 256 + j], d_phi[e * 256 + j]);
            float angm = fmaf(mv, m_frq[e * 256 + j], m_phi[e * 256 + j]);
            float ad = d_amp[e * 128 + jm];
            float am = m_amp[e * 128 + jm];
            ot[j] = (j < 128) ? (ad * __cosf(angd) + am * __cosf(angm))
                              : (ad * __sinf(angd) + am * __sinf(angm));
        }
    }
    __syncthreads();

    // ---- write A row: Adiff (bf16x2, coalesced) ----
    const size_t sb = (size_t)s_idx * 512;
    const size_t ob = (size_t)o_idx * 512;
    {
        int k = tid * 2;
        float2 es = *reinterpret_cast<const float2*>(e_emb + sb + k);
        float2 eo = *reinterpret_cast<const float2*>(e_emb + ob + k);
        __nv_bfloat162 h = __floats2bfloat162_rn(es.x - eo.x, es.y - eo.y);
        *reinterpret_cast<unsigned*>(&g_AB[(size_t)b * KTOT + k]) =
            *reinterpret_cast<unsigned*>(&h);
    }
    // ---- write A row: W histogram (4 floats -> 2x bf16x2 = 8B, coalesced) ----
    {
        int k = tid * 4;
        __nv_bfloat162 h0 = __floats2bfloat162_rn(Wrow[k], Wrow[k + 1]);
        __nv_bfloat162 h1 = __floats2bfloat162_rn(Wrow[k + 2], Wrow[k + 3]);
        uint2 q;
        q.x = *reinterpret_cast<unsigned*>(&h0);
        q.y = *reinterpret_cast<unsigned*>(&h1);
        *reinterpret_cast<uint2*>(&g_AB[(size_t)b * KTOT + KA + k]) = q;
    }

    // ---- sc_abs over k = 0..383 ----
    const float scale = (float)(3.141592653589793 / sqrt(6.0 / (double)(NR_ + RDIM_)));
    float sum = 0.0f;
    for (int k = tid; k < 384; k += 256) {
        float pr = r_emb[(size_t)r_idx * 384 + k] * scale;
        float sn, cs;
        __sincosf(pr, &sn, &cs);
        float re_s, im_s, re_o, im_o;
        if (k < 256) {
            re_s = e_emb[sb + k];
            im_s = e_emb[sb + 256 + k];
            re_o = e_emb[ob + k];
            im_o = e_emb[ob + 256 + k];
        } else {
            re_s = st[k - 256];  im_s = st[k - 128];
            re_o = ot[k - 256];  im_o = ot[k - 128];
        }
        float re = re_s * cs - im_s * sn - re_o;
        float im = re_s * sn + im_s * cs - im_o;
        sum += sqrtf(re * re + im * im);
    }

    #pragma unroll
    for (int off = 16; off; off >>= 1) sum += __shfl_down_sync(0xffffffffu, sum, off);
    if ((tid & 31) == 0) red8[tid >> 5] = sum;
    __syncthreads();
    if (tid == 0) {
        float t = 0.0f;
        #pragma unroll
        for (int i = 0; i < 8; i++) t += red8[i];
        g_scabs[b] = t;
    }
}

// ======================================================================
// Launch 3: bf16 HMMA GEMM.  D[8192 x 256] = g_AB @ g_Bm^T
//   BM=128, BN=128, BK=32, 8 warps, warp tile 64x32 (4x4 m16n8k16 frags)
//   all-bf16 staging = straight uint4 copies.
// ======================================================================
#define PADK 40

__device__ __forceinline__ void mma16816(float* c, const uint32_t* a, const uint32_t* b) {
    asm volatile(
        "mma.sync.aligned.m16n8k16.row.col.f32.bf16.bf16.f32 "
        "{%0,%1,%2,%3}, {%4,%5,%6,%7}, {%8,%9}, {%0,%1,%2,%3};"
        : "+f"(c[0]), "+f"(c[1]), "+f"(c[2]), "+f"(c[3])
        : "r"(a[0]), "r"(a[1]), "r"(a[2]), "r"(a[3]), "r"(b[0]), "r"(b[1]));
}

__global__ void __launch_bounds__(256) k_gemm() {
    __shared__ __nv_bfloat16 As[128 * PADK];   // 10 KB
    __shared__ __nv_bfloat16 Bs[128 * PADK];   // 10 KB

    const int tid  = threadIdx.x;
    const int wid  = tid >> 5;
    const int lane = tid & 31;
    const int bn = blockIdx.x * 128;
    const int bm = blockIdx.y * 128;

    const int wm = wid & 1;
    const int wn = wid >> 1;
    const int gid = lane >> 2;          // 0..7
    const int tig = lane & 3;           // 0..3

    const int sr = tid >> 1;            // A row / B n-row (0..127)
    const int sk = (tid & 1) * 16;      // k half (0 or 16)
    const __nv_bfloat16* aptr = g_AB + (size_t)(bm + sr) * KTOT;
    const __nv_bfloat16* bptr = g_Bm + (size_t)(bn + sr) * KTOT;

    float acc[4][4][4];
    #pragma unroll
    for (int i = 0; i < 4; i++)
        #pragma unroll
        for (int j = 0; j < 4; j++)
            #pragma unroll
            for (int e = 0; e < 4; e++) acc[i][j][e] = 0.0f;

    for (int k0 = 0; k0 < KTOT; k0 += 32) {
        {
            uint4 q0 = __ldg(reinterpret_cast<const uint4*>(aptr + k0 + sk));
            uint4 q1 = __ldg(reinterpret_cast<const uint4*>(aptr + k0 + sk + 8));
            *reinterpret_cast<uint4*>(&As[sr * PADK + sk])     = q0;
            *reinterpret_cast<uint4*>(&As[sr * PADK + sk + 8]) = q1;
        }
        {
            uint4 q0 = __ldg(reinterpret_cast<const uint4*>(bptr + k0 + sk));
            uint4 q1 = __ldg(reinterpret_cast<const uint4*>(bptr + k0 + sk + 8));
            *reinterpret_cast<uint4*>(&Bs[sr * PADK + sk])     = q0;
            *reinterpret_cast<uint4*>(&Bs[sr * PADK + sk + 8]) = q1;
        }
        __syncthreads();

        #pragma unroll
        for (int ks = 0; ks < 32; ks += 16) {
            uint32_t afr[4][4], bfr[4][2];
            #pragma unroll
            for (int i = 0; i < 4; i++) {
                int row = wm * 64 + i * 16 + gid;
                afr[i][0] = *reinterpret_cast<const uint32_t*>(&As[row * PADK + ks + tig * 2]);
                afr[i][1] = *reinterpret_cast<const uint32_t*>(&As[(row + 8) * PADK + ks + tig * 2]);
                afr[i][2] = *reinterpret_cast<const uint32_t*>(&As[row * PADK + ks + 8 + tig * 2]);
                afr[i][3] = *reinterpret_cast<const uint32_t*>(&As[(row + 8) * PADK + ks + 8 + tig * 2]);
            }
            #pragma unroll
            for (int j = 0; j < 4; j++) {
                int nc = wn * 32 + j * 8 + gid;
                bfr[j][0] = *reinterpret_cast<const uint32_t*>(&Bs[nc * PADK + ks + tig * 2]);
                bfr[j][1] = *reinterpret_cast<const uint32_t*>(&Bs[nc * PADK + ks + 8 + tig * 2]);
            }
            #pragma unroll
            for (int i = 0; i < 4; i++)
                #pragma unroll
                for (int j = 0; j < 4; j++)
                    mma16816(acc[i][j], afr[i], bfr[j]);
        }
        __syncthreads();
    }

    #pragma unroll
    for (int i = 0; i < 4; i++) {
        int row = bm + wm * 64 + i * 16 + gid;
        #pragma unroll
        for (int j = 0; j < 4; j++) {
            int col = bn + wn * 32 + j * 8 + tig * 2;
            *reinterpret_cast<float2*>(&g_D[(size_t)row * 256 + col]) =
                make_float2(acc[i][j][0], acc[i][j][1]);
            *reinterpret_cast<float2*>(&g_D[(size_t)(row + 8) * 256 + col]) =
                make_float2(acc[i][j][2], acc[i][j][3]);
        }
    }
}

// ======================================================================
// Launch 4: final — sc_rel distances from D, combine with sc_abs
// ======================================================================
__global__ void __launch_bounds__(128) k_fin(float* __restrict__ out) {
    __shared__ float red4[4];
    const int row = blockIdx.x;
    const int d   = threadIdx.x;   // 0..127

    float dre = g_D[(size_t)row * 256 + d];
    float dim = g_D[(size_t)row * 256 + 128 + d];
    float v = sqrtf(dre * dre + dim * dim);

    #pragma unroll
    for (int off = 16; off; off >>= 1) v += __shfl_down_sync(0xffffffffu, v, off);
    if ((d & 31) == 0) red4[d >> 5] = v;
    __syncthreads();
    if (d == 0)
        out[row] = GAMMA_F - (g_scabs[row] + red4[0] + red4[1] + red4[2] + red4[3]);
}

// ======================================================================
// launcher
// ======================================================================
extern "C" void kernel_launch(void* const* d_in, const int* in_sizes, int n_in,
                              void* d_out, int out_size)
{
    const int*   x     = (const int*)  d_in[0];
    const float* e_emb = (const float*)d_in[1];
    const float* r_emb = (const float*)d_in[2];
    const float* d_frq = (const float*)d_in[3];
    const float* d_phi = (const float*)d_in[4];
    const float* d_amp = (const float*)d_in[5];
    const float* m_frq = (const float*)d_in[6];
    const float* m_phi = (const float*)d_in[7];
    const float* m_amp = (const float*)d_in[8];
    const float* w_e   = (const float*)d_in[9];
    const float* w_rp  = (const float*)d_in[10];
    float* out = (float*)d_out;

    // x arrives as int64 reported in int32 words; infer element stride.
    int xs = in_sizes[0] / (BB * NCOL);
    if (xs < 1) xs = 1;

    k_pre<<<256, 512>>>(w_e);
    k_gather<<<BB, 256>>>(x, xs, e_emb, r_emb, d_frq, d_phi, d_amp,
                          m_frq, m_phi, m_amp, w_rp);
    k_gemm<<<dim3(2, 64), 256>>>();
    k_fin<<<BB, 128>>>(out);
}

// round 16
// speedup vs baseline: 3.7604x; 1.2941x over previous
#include <cuda_runtime.h>
#include <cuda_bf16.h>
#include <math.h>
#include <stdint.h>

// ---------------- problem constants ----------------
#define NE_    100000
#define NR_    200
#define RDIM_  384
#define BB     8192
#define NCOL   406          // 6 scalar cols + 2*NR
#define GAMMA_F 12.0f
#define KA     512          // Adiff K-region
#define KW     1024         // W (t-histogram) K-region, t in [0,1000) zero-padded
#define KTOT   (KA + KW)    // 1536

#define LOGK (13.287712379549449f / 128.0f)   // log2(10000)/128

// ---------------- scratch (__device__ globals; no allocs allowed) ----------------
__device__ float    g_scabs[BB];                          // per-row sc_abs
__device__ __align__(16) __nv_bfloat16 g_AB[BB * KTOT];   // A: [Adiff | W] per row (24 MB)
__device__ __align__(16) __nv_bfloat16 g_Bm[256 * KTOT];  // B: [Wc ; PosTable] (768 KB)
__device__ float    g_D[BB * 256];                        // GEMM result (8 MB)

// ======================================================================
// PTX helpers
// ======================================================================
__device__ __forceinline__ uint32_t smem_u32(const void* p) {
    uint32_t a;
    asm("{ .reg .u64 t; cvta.to.shared.u64 t, %1; cvt.u32.u64 %0, t; }" : "=r"(a) : "l"(p));
    return a;
}
__device__ __forceinline__ void cp_async16(uint32_t dst, const void* src) {
    asm volatile("cp.async.cg.shared.global [%0], [%1], 16;" :: "r"(dst), "l"(src));
}
__device__ __forceinline__ void cp_commit() {
    asm volatile("cp.async.commit_group;");
}
__device__ __forceinline__ void cp_wait0() {
    asm volatile("cp.async.wait_group 0;");
}
__device__ __forceinline__ void ldmatrix_x4(uint32_t* r, uint32_t addr) {
    asm volatile("ldmatrix.sync.aligned.m8n8.x4.shared.b16 {%0,%1,%2,%3}, [%4];"
                 : "=r"(r[0]), "=r"(r[1]), "=r"(r[2]), "=r"(r[3]) : "r"(addr));
}
__device__ __forceinline__ void mma16816(float* c, const uint32_t* a, const uint32_t* b) {
    asm volatile(
        "mma.sync.aligned.m16n8k16.row.col.f32.bf16.bf16.f32 "
        "{%0,%1,%2,%3}, {%4,%5,%6,%7}, {%8,%9}, {%0,%1,%2,%3};"
        : "+f"(c[0]), "+f"(c[1]), "+f"(c[2]), "+f"(c[3])
        : "r"(a[0]), "r"(a[1]), "r"(a[2]), "r"(a[3]), "r"(b[0]), "r"(b[1]));
}

// ======================================================================
// Launch 1: build B operand g_Bm[n][k]  (unchanged from R15)
// ======================================================================
__global__ void __launch_bounds__(512) k_pre(const float* __restrict__ w_e) {
    const int n = blockIdx.x;       // 0..255
    const int tid = threadIdx.x;
    const float f = exp2f(-(float)(n & 127) * LOGK);
    for (int k = tid; k < KTOT; k += 512) {
        float v;
        if (k < KA) {
            if (n < 128) {
                v = w_e[k * 128 + n];
                if (k >= 256) v = -v;
            } else {
                v = w_e[(k ^ 256) * 128 + (n - 128)];
                if (k < 256) v = -v;
            }
        } else if (k < KA + 1000) {
            float t = (float)(k - KA);
            float s, c;
            sincosf(t * f, &s, &c);
            v = (n < 128) ? c : s;
        } else {
            v = 0.0f;
        }
        g_Bm[n * KTOT + k] = __float2bfloat16(v);
    }
}

// ======================================================================
// Launch 2: per row — signed t-histogram W, Adiff, t_emb, sc_abs
// (unchanged from R15)
// ======================================================================
__global__ void __launch_bounds__(256) k_gather(
    const int* __restrict__ x, int xs,
    const float* __restrict__ e_emb,
    const float* __restrict__ r_emb,
    const float* __restrict__ d_frq, const float* __restrict__ d_phi,
    const float* __restrict__ d_amp,
    const float* __restrict__ m_frq, const float* __restrict__ m_phi,
    const float* __restrict__ m_amp,
    const float* __restrict__ w_rp)
{
    __shared__ float Wrow[KW];      // signed histogram over t
    __shared__ float st[256];
    __shared__ float ot[256];
    __shared__ float red8[8];

    const int b   = blockIdx.x;
    const int tid = threadIdx.x;
    const int base = b * NCOL;

    #pragma unroll
    for (int i = 0; i < 4; i++) Wrow[tid + i * 256] = 0.0f;
    __syncthreads();

    const int s_idx = x[(base + 0) * xs];
    const int r_idx = x[(base + 1) * xs];
    const int o_idx = x[(base + 2) * xs];
    const float dv  = (float)x[(base + 3) * xs];
    const float mv  = (float)x[(base + 4) * xs];

    for (int i = tid; i < 400; i += 256) {
        int side = (i >= 200);
        int n    = i - side * 200;
        int t    = x[(base + 6 + i) * xs];
        float w  = w_rp[r_idx * 200 + n];
        atomicAdd(&Wrow[t], side ? -w : w);
    }

    {
        const int j  = tid;
        const int jm = (j < 128) ? j : (j - 128);
        {
            const size_t e = (size_t)s_idx;
            float angd = fmaf(dv, d_frq[e * 256 + j], d_phi[e * 256 + j]);
            float angm = fmaf(mv, m_frq[e * 256 + j], m_phi[e * 256 + j]);
            float ad = d_amp[e * 128 + jm];
            float am = m_amp[e * 128 + jm];
            st[j] = (j < 128) ? (ad * __cosf(angd) + am * __cosf(angm))
                              : (ad * __sinf(angd) + am * __sinf(angm));
        }
        {
            const size_t e = (size_t)o_idx;
            float angd = fmaf(dv, d_frq[e * 256 + j], d_phi[e * 256 + j]);
            float angm = fmaf(mv, m_frq[e * 256 + j], m_phi[e * 256 + j]);
            float ad = d_amp[e * 128 + jm];
            float am = m_amp[e * 128 + jm];
            ot[j] = (j < 128) ? (ad * __cosf(angd) + am * __cosf(angm))
                              : (ad * __sinf(angd) + am * __sinf(angm));
        }
    }
    __syncthreads();

    const size_t sb = (size_t)s_idx * 512;
    const size_t ob = (size_t)o_idx * 512;
    {
        int k = tid * 2;
        float2 es = *reinterpret_cast<const float2*>(e_emb + sb + k);
        float2 eo = *reinterpret_cast<const float2*>(e_emb + ob + k);
        __nv_bfloat162 h = __floats2bfloat162_rn(es.x - eo.x, es.y - eo.y);
        *reinterpret_cast<unsigned*>(&g_AB[(size_t)b * KTOT + k]) =
            *reinterpret_cast<unsigned*>(&h);
    }
    {
        int k = tid * 4;
        __nv_bfloat162 h0 = __floats2bfloat162_rn(Wrow[k], Wrow[k + 1]);
        __nv_bfloat162 h1 = __floats2bfloat162_rn(Wrow[k + 2], Wrow[k + 3]);
        uint2 q;
        q.x = *reinterpret_cast<unsigned*>(&h0);
        q.y = *reinterpret_cast<unsigned*>(&h1);
        *reinterpret_cast<uint2*>(&g_AB[(size_t)b * KTOT + KA + k]) = q;
    }

    const float scale = (float)(3.141592653589793 / sqrt(6.0 / (double)(NR_ + RDIM_)));
    float sum = 0.0f;
    for (int k = tid; k < 384; k += 256) {
        float pr = r_emb[(size_t)r_idx * 384 + k] * scale;
        float sn, cs;
        __sincosf(pr, &sn, &cs);
        float re_s, im_s, re_o, im_o;
        if (k < 256) {
            re_s = e_emb[sb + k];
            im_s = e_emb[sb + 256 + k];
            re_o = e_emb[ob + k];
            im_o = e_emb[ob + 256 + k];
        } else {
            re_s = st[k - 256];  im_s = st[k - 128];
            re_o = ot[k - 256];  im_o = ot[k - 128];
        }
        float re = re_s * cs - im_s * sn - re_o;
        float im = re_s * sn + im_s * cs - im_o;
        sum += sqrtf(re * re + im * im);
    }

    #pragma unroll
    for (int off = 16; off; off >>= 1) sum += __shfl_down_sync(0xffffffffu, sum, off);
    if ((tid & 31) == 0) red8[tid >> 5] = sum;
    __syncthreads();
    if (tid == 0) {
        float t = 0.0f;
        #pragma unroll
        for (int i = 0; i < 8; i++) t += red8[i];
        g_scabs[b] = t;
    }
}

// ======================================================================
// Launch 3: bf16 HMMA GEMM, cp.async double-buffered + ldmatrix frags.
//   D[8192 x 256] = g_AB @ g_Bm^T
//   BM=64, BN=128, BK=32, 256 thr (8 warps, 2m x 4n), warp tile 32x32
// ======================================================================
#define PADK 40
#define NIT  (KTOT / 32)     // 48

__global__ void __launch_bounds__(256) k_gemm() {
    __shared__ __nv_bfloat16 As[2][64 * PADK];    // 2 x 5 KB
    __shared__ __nv_bfloat16 Bs[2][128 * PADK];   // 2 x 10 KB

    const int tid  = threadIdx.x;
    const int wid  = tid >> 5;
    const int lane = tid & 31;
    const int bn = blockIdx.x * 128;
    const int bm = blockIdx.y * 64;
    const int wm = wid & 1;          // m warp (32 rows)
    const int wn = wid >> 1;         // n warp (32 cols)

    // cp.async staging: A 64x32 (4KB) 1 chunk/thr; B 128x32 (8KB) 2 chunks/thr
    const int ar = tid >> 2;         // 0..63
    const int ac = (tid & 3) * 8;    // 0,8,16,24
    const __nv_bfloat16* agp  = g_AB + (size_t)(bm + ar) * KTOT + ac;
    const __nv_bfloat16* bgp0 = g_Bm + (size_t)(bn + ar) * KTOT + ac;
    const __nv_bfloat16* bgp1 = g_Bm + (size_t)(bn + 64 + ar) * KTOT + ac;

    const uint32_t sA0 = smem_u32(&As[0][0]);
    const uint32_t sB0 = smem_u32(&Bs[0][0]);
    const uint32_t aDst = (uint32_t)((ar * PADK + ac) * 2);
    const uint32_t bDst0 = aDst;
    const uint32_t bDst1 = (uint32_t)(((64 + ar) * PADK + ac) * 2);
    const uint32_t bufA = 64 * PADK * 2;     // byte stride between A buffers
    const uint32_t bufB = 128 * PADK * 2;

    // fragment-load lane addressing
    const int arow = lane & 15;              // ldmatrix A row within 16
    const int acol = (lane >> 4) * 8;        // A k offset
    const int bnrw = ((lane >> 4) * 8) + (lane & 7);   // B n row within 16
    const int bcol = ((lane >> 3) & 1) * 8;            // B k offset

    float acc[2][4][4];
    #pragma unroll
    for (int i = 0; i < 2; i++)
        #pragma unroll
        for (int j = 0; j < 4; j++)
            #pragma unroll
            for (int e = 0; e < 4; e++) acc[i][j][e] = 0.0f;

    // prologue: stage tile 0 into buffer 0
    cp_async16(sA0 + aDst, agp);
    cp_async16(sB0 + bDst0, bgp0);
    cp_async16(sB0 + bDst1, bgp1);
    cp_commit();

    for (int it = 0; it < NIT; it++) {
        const int buf = it & 1;
        cp_wait0();
        __syncthreads();

        if (it + 1 < NIT) {
            const int nb = buf ^ 1;
            const int k0 = (it + 1) * 32;
            cp_async16(sA0 + nb * bufA + aDst, agp + k0);
            cp_async16(sB0 + nb * bufB + bDst0, bgp0 + k0);
            cp_async16(sB0 + nb * bufB + bDst1, bgp1 + k0);
            cp_commit();
        }

        const uint32_t sAb = sA0 + buf * bufA;
        const uint32_t sBb = sB0 + buf * bufB;

        #pragma unroll
        for (int ks = 0; ks < 32; ks += 16) {
            uint32_t af[2][4];
            #pragma unroll
            for (int i = 0; i < 2; i++) {
                uint32_t addr = sAb + (uint32_t)(((wm * 32 + i * 16 + arow) * PADK
                                                 + ks + acol) * 2);
                ldmatrix_x4(af[i], addr);
            }
            uint32_t bf[4][2];
            #pragma unroll
            for (int jt = 0; jt < 2; jt++) {
                uint32_t q[4];
                uint32_t addr = sBb + (uint32_t)(((wn * 32 + jt * 16 + bnrw) * PADK
                                                 + ks + bcol) * 2);
                ldmatrix_x4(q, addr);
                bf[jt * 2][0] = q[0]; bf[jt * 2][1] = q[1];
                bf[jt * 2 + 1][0] = q[2]; bf[jt * 2 + 1][1] = q[3];
            }
            #pragma unroll
            for (int i = 0; i < 2; i++)
                #pragma unroll
                for (int j = 0; j < 4; j++)
                    mma16816(acc[i][j], af[i], bf[j]);
        }
        __syncthreads();
    }

    const int gid = lane >> 2;
    const int tig = lane & 3;
    #pragma unroll
    for (int i = 0; i < 2; i++) {
        int row = bm + wm * 32 + i * 16 + gid;
        #pragma unroll
        for (int j = 0; j < 4; j++) {
            int col = bn + wn * 32 + j * 8 + tig * 2;
            *reinterpret_cast<float2*>(&g_D[(size_t)row * 256 + col]) =
                make_float2(acc[i][j][0], acc[i][j][1]);
            *reinterpret_cast<float2*>(&g_D[(size_t)(row + 8) * 256 + col]) =
                make_float2(acc[i][j][2], acc[i][j][3]);
        }
    }
}

// ======================================================================
// Launch 4: final — warp per row (4 rows/warp), float4 loads.
// ======================================================================
__global__ void __launch_bounds__(256) k_fin(float* __restrict__ out) {
    const int lane = threadIdx.x & 31;
    const int gw   = blockIdx.x * 8 + (threadIdx.x >> 5);   // global warp id

    #pragma unroll
    for (int rr = 0; rr < 4; rr++) {
        const int row = gw * 4 + rr;
        float4 re = *reinterpret_cast<const float4*>(&g_D[(size_t)row * 256 + lane * 4]);
        float4 im = *reinterpret_cast<const float4*>(&g_D[(size_t)row * 256 + 128 + lane * 4]);
        float v = sqrtf(re.x * re.x + im.x * im.x)
                + sqrtf(re.y * re.y + im.y * im.y)
                + sqrtf(re.z * re.z + im.z * im.z)
                + sqrtf(re.w * re.w + im.w * im.w);
        #pragma unroll
        for (int off = 16; off; off >>= 1) v += __shfl_down_sync(0xffffffffu, v, off);
        if (lane == 0) out[row] = GAMMA_F - (g_scabs[row] + v);
    }
}

// ======================================================================
// launcher
// ======================================================================
extern "C" void kernel_launch(void* const* d_in, const int* in_sizes, int n_in,
                              void* d_out, int out_size)
{
    const int*   x     = (const int*)  d_in[0];
    const float* e_emb = (const float*)d_in[1];
    const float* r_emb = (const float*)d_in[2];
    const float* d_frq = (const float*)d_in[3];
    const float* d_phi = (const float*)d_in[4];
    const float* d_amp = (const float*)d_in[5];
    const float* m_frq = (const float*)d_in[6];
    const float* m_phi = (const float*)d_in[7];
    const float* m_amp = (const float*)d_in[8];
    const float* w_e   = (const float*)d_in[9];
    const float* w_rp  = (const float*)d_in[10];
    float* out = (float*)d_out;

    // x arrives as int64 reported in int32 words; infer element stride.
    int xs = in_sizes[0] / (BB * NCOL);
    if (xs < 1) xs = 1;

    k_pre<<<256, 512>>>(w_e);
    k_gather<<<BB, 256>>>(x, xs, e_emb, r_emb, d_frq, d_phi, d_amp,
                          m_frq, m_phi, m_amp, w_rp);
    k_gemm<<<dim3(2, 128), 256>>>();
    k_fin<<<256, 256>>>(out);
}